// round 16
// baseline (speedup 1.0000x reference)
#include <cuda_runtime.h>
#include <cuda_fp16.h>
#include <cstdint>
#include <math.h>

// tril(A @ B), A,B lower-triangular fp32, N=4096.
// R16 = R15 (best: 166us) + split-K on the 91 largest-K tiles:
//   corner CTAs ran 126 chunk-units vs 80.9/slot ideal -> makespan-bound.
//   Tiles t<91 (d>=19, strictly sub-diagonal): each half-tile splits into
//   two k-segments (<=63 units). Seg0 -> C direct (no mask needed),
//   seg1 -> static scratch, combine kernel adds back. Deterministic.
// Numerics unchanged: x = h + l (fp16 exact residual); D = Ah*Bh + Al*Bh.

#define NDIM 4096
#define NB   32
#define BK   32
#define THREADS 256

#define ST_AH 0                // A hi: 128 rows * 64B = 8192
#define ST_AL 8192             // A lo: 8192
#define ST_BH 16384            // B hi: 32 k-rows * 128B = 4096
#define STAGE 20480
#define SMEM_DYN (2 * STAGE)   // 40960/CTA; x2 CTAs = 81920

#define NSPLIT_T   91          // tiles t<91 have d>=19 (nc>=78) -> split
#define SPLIT_CTAS (NSPLIT_T * 4)          // 364: (t, half, seg)
__device__ float g_S[NSPLIT_T * 2 * 128 * 64];   // 5.96MB seg1 partials

static __device__ __forceinline__ uint32_t smem_u32(const void* p) {
    uint32_t a;
    asm("{ .reg .u64 t; cvta.to.shared.u64 t, %1; cvt.u32.u64 %0, t; }"
        : "=r"(a) : "l"(p));
    return a;
}

static __device__ __forceinline__ uint32_t h2u(__half2 h) {
    return *reinterpret_cast<uint32_t*>(&h);
}

static __device__ __forceinline__ void split2(float x, float y,
                                              uint32_t& h, uint32_t& l) {
    __half2 hh = __floats2half2_rn(x, y);
    float rx = x - __half2float(__low2half(hh));
    float ry = y - __half2float(__high2half(hh));
    l = h2u(__floats2half2_rn(rx, ry));
    h = h2u(hh);
}

static __device__ __forceinline__ void ldm4(uint32_t d[4], uint32_t addr) {
    asm volatile("ldmatrix.sync.aligned.m8n8.x4.shared.b16 {%0,%1,%2,%3}, [%4];"
                 : "=r"(d[0]), "=r"(d[1]), "=r"(d[2]), "=r"(d[3]) : "r"(addr));
}
static __device__ __forceinline__ void ldm4t(uint32_t d[4], uint32_t addr) {
    asm volatile("ldmatrix.sync.aligned.m8n8.x4.trans.shared.b16 {%0,%1,%2,%3}, [%4];"
                 : "=r"(d[0]), "=r"(d[1]), "=r"(d[2]), "=r"(d[3]) : "r"(addr));
}

static __device__ __forceinline__ void mma_f16(float* c, const uint32_t* a,
                                               const uint32_t* b) {
    asm volatile(
        "mma.sync.aligned.m16n8k16.row.col.f32.f16.f16.f32 "
        "{%0,%1,%2,%3}, {%4,%5,%6,%7}, {%8,%9}, {%0,%1,%2,%3};"
        : "+f"(c[0]), "+f"(c[1]), "+f"(c[2]), "+f"(c[3])
        : "r"(a[0]), "r"(a[1]), "r"(a[2]), "r"(a[3]), "r"(b[0]), "r"(b[1]));
}

static __device__ __forceinline__ void split4(float4 v, uint32_t& h01, uint32_t& h23,
                                              uint32_t& l01, uint32_t& l23) {
    split2(v.x, v.y, h01, l01);
    split2(v.z, v.w, h23, l23);
}

static __device__ __forceinline__ void sts2(uint32_t addr, uint32_t a, uint32_t b) {
    asm volatile("st.shared.v2.b32 [%0], {%1,%2};" :: "r"(addr), "r"(a), "r"(b)
                 : "memory");
}

__global__ __launch_bounds__(THREADS, 2)
void trimm_f16(const float* __restrict__ A, const float* __restrict__ B,
               float* __restrict__ C)
{
    extern __shared__ __align__(128) char dyn_smem[];
    const uint32_t sbase = smem_u32(dyn_smem);

    const int tid  = threadIdx.x;
    const int wid  = tid >> 5;
    const int lane = tid & 31;

    // ---- block id -> (tile t, half, seg); split segments scheduled first ----
    const int bid = blockIdx.x;
    int t, half, seg;
    if (bid < SPLIT_CTAS) { t = bid >> 2; half = (bid >> 1) & 1; seg = bid & 1; }
    else { int r = bid - SPLIT_CTAS; t = NSPLIT_T + (r >> 1); half = r & 1; seg = 0; }

    int g = (int)((sqrtf(8.0f * (float)t + 1.0f) - 1.0f) * 0.5f);
    while ((g + 1) * (g + 2) / 2 <= t) ++g;
    while (g * (g + 1) / 2 > t) --g;
    const int bj = t - g * (g + 1) / 2;
    const int bi = bj + (NB - 1) - g;
    const int bm0 = bi * 128;
    const int bn0 = bj * 128 + half * 64;

    const int ncTot = ((bm0 + 128) - bn0) >> 5;         // total chunks (even)
    const bool isSplit = (t < NSPLIT_T);
    const int cBeg = (isSplit && seg) ? (ncTot >> 1) : 0;
    const int cEnd = (isSplit && !seg) ? (ncTot >> 1) : ncTot;
    const int nchunks = cEnd - cBeg;                     // >= 1 always
    const int kStart = bn0 + cBeg * BK;

    // warp grid: 4(m) x 2(n); warp tile 32x32
    const int m0w = (wid & 3) * 32;
    const int n0w = (wid >> 2) * 32;

    // ---- A-tile ldmatrix lane address (64B rows, chunk ^= (r>>1)&3) ----
    const uint32_t swL   = (uint32_t)(((lane & 15) >> 1) & 3);
    const uint32_t laneA = (uint32_t)((lane & 15) * 64) +
                           ((((uint32_t)(lane >> 4)) ^ swL) << 4);
    const uint32_t laneBRow = (uint32_t)((lane & 15) * 128);
    const uint32_t laneBCol = (uint32_t)((((lane >> 4) ^ (lane & 7)) << 4));

    // ---- global load + A-store indices ----
    const int amRow = tid >> 3;
    const int akOff = (tid & 7) * 4;
    const int bkRow = tid >> 4;
    const int bnOff = (tid & 15) * 4;
    const uint32_t aoffBase = (uint32_t)(amRow * 64) +
        ((((uint32_t)((tid & 7) >> 1)) ^ ((uint32_t)(tid >> 4) & 3u)) << 4) +
        (uint32_t)((tid & 1) * 8);

    float acc[2][4][4];
#pragma unroll
    for (int mt = 0; mt < 2; ++mt)
#pragma unroll
        for (int nt = 0; nt < 4; ++nt)
#pragma unroll
            for (int e = 0; e < 4; ++e) acc[mt][nt][e] = 0.0f;

    float4 ra[4], rb[2];

#define LOAD_CHUNK(k0)                                                          \
    {                                                                           \
        _Pragma("unroll")                                                       \
        for (int p = 0; p < 4; ++p)                                             \
            ra[p] = *(const float4*)(A + (size_t)(bm0 + amRow + p * 32) * NDIM  \
                                       + (k0) + akOff);                         \
        _Pragma("unroll")                                                       \
        for (int p = 0; p < 2; ++p)                                             \
            rb[p] = *(const float4*)(B + (size_t)((k0) + bkRow + p * 16) * NDIM \
                                       + bn0 + bnOff);                          \
    }

#define STORE_CHUNK(sbuf)                                                       \
    {                                                                           \
        _Pragma("unroll")                                                       \
        for (int p = 0; p < 4; ++p) {                                           \
            uint32_t h01, h23, l01, l23;                                        \
            split4(ra[p], h01, h23, l01, l23);                                  \
            uint32_t aoff = aoffBase + (uint32_t)(p * 2048);                    \
            sts2((sbuf) + ST_AH + aoff, h01, h23);                              \
            sts2((sbuf) + ST_AL + aoff, l01, l23);                              \
        }                                                                       \
        _Pragma("unroll")                                                       \
        for (int p = 0; p < 2; ++p) {                                           \
            __half2 h0 = __floats2half2_rn(rb[p].x, rb[p].y);                   \
            __half2 h1 = __floats2half2_rn(rb[p].z, rb[p].w);                   \
            int kk = bkRow + p * 16;                                            \
            uint32_t boff = (uint32_t)(kk * 128 +                               \
                            ((bnOff * 2) ^ ((kk & 7) << 4)));                   \
            sts2((sbuf) + ST_BH + boff, h2u(h0), h2u(h1));                      \
        }                                                                       \
    }

    // prologue
    LOAD_CHUNK(kStart);
    STORE_CHUNK(sbase);
    __syncthreads();

    for (int c = 0; c < nchunks; ++c) {
        const uint32_t scur = sbase + (uint32_t)(c & 1) * STAGE;
        const bool more = (c + 1 < nchunks);
        if (more) LOAD_CHUNK(kStart + (c + 1) * BK);

#pragma unroll
        for (int ks = 0; ks < BK; ks += 16) {
            uint32_t aH[2][4], aL[2][4], bF[2][4];
#pragma unroll
            for (int mt = 0; mt < 2; ++mt) {
                uint32_t ar = scur + ST_AH +
                              (uint32_t)((m0w + 16 * mt) * 64) +
                              (laneA ^ (uint32_t)((ks >> 3) << 4));
                ldm4(aH[mt], ar);
                ldm4(aL[mt], ar + (ST_AL - ST_AH));
            }
#pragma unroll
            for (int ntp = 0; ntp < 2; ++ntp) {
                uint32_t twoN0 = (uint32_t)((n0w + 16 * ntp) * 2);
                uint32_t br = scur + ST_BH + (uint32_t)(ks * 128) + laneBRow +
                              (twoN0 ^ laneBCol);
                ldm4t(bF[ntp], br);
            }
#pragma unroll
            for (int mt = 0; mt < 2; ++mt)
#pragma unroll
                for (int nt = 0; nt < 4; ++nt)
                    mma_f16(acc[mt][nt], aH[mt], &bF[nt >> 1][(nt & 1) * 2]);
#pragma unroll
            for (int mt = 0; mt < 2; ++mt)
#pragma unroll
                for (int nt = 0; nt < 4; ++nt)
                    mma_f16(acc[mt][nt], aL[mt], &bF[nt >> 1][(nt & 1) * 2]);
        }

        if (more) STORE_CHUNK(sbase + (uint32_t)((c + 1) & 1) * STAGE);
        __syncthreads();
    }

    // ---- epilogue ----
    if (isSplit && seg) {
        // seg1 partial -> scratch (local [128][64], row-major)
        float* S = g_S + (size_t)(t * 2 + half) * 8192;
#pragma unroll
        for (int mt = 0; mt < 2; ++mt) {
            const int rl = m0w + 16 * mt + (lane >> 2);
#pragma unroll
            for (int nt = 0; nt < 4; ++nt) {
                const int cl = n0w + 8 * nt + 2 * (lane & 3);
                S[rl * 64 + cl]           = acc[mt][nt][0];
                S[rl * 64 + cl + 1]       = acc[mt][nt][1];
                S[(rl + 8) * 64 + cl]     = acc[mt][nt][2];
                S[(rl + 8) * 64 + cl + 1] = acc[mt][nt][3];
            }
        }
    } else if (isSplit) {
        // split tiles are strictly sub-diagonal: no mask
#pragma unroll
        for (int mt = 0; mt < 2; ++mt) {
            const int r0 = bm0 + m0w + 16 * mt + (lane >> 2);
#pragma unroll
            for (int nt = 0; nt < 4; ++nt) {
                const int c0 = bn0 + n0w + 8 * nt + 2 * (lane & 3);
                float* p0 = C + (size_t)r0 * NDIM + c0;
                float* p1 = p0 + 8 * (size_t)NDIM;
                p0[0] = acc[mt][nt][0];
                p0[1] = acc[mt][nt][1];
                p1[0] = acc[mt][nt][2];
                p1[1] = acc[mt][nt][3];
            }
        }
    } else {
#pragma unroll
        for (int mt = 0; mt < 2; ++mt) {
            const int r0 = bm0 + m0w + 16 * mt + (lane >> 2);
#pragma unroll
            for (int nt = 0; nt < 4; ++nt) {
                const int c0 = bn0 + n0w + 8 * nt + 2 * (lane & 3);
                float* p0 = C + (size_t)r0 * NDIM + c0;
                float* p1 = p0 + 8 * (size_t)NDIM;
                if (c0     <= r0)     p0[0] = acc[mt][nt][0];
                if (c0 + 1 <= r0)     p0[1] = acc[mt][nt][1];
                if (c0     <= r0 + 8) p1[0] = acc[mt][nt][2];
                if (c0 + 1 <= r0 + 8) p1[1] = acc[mt][nt][3];
            }
        }
    }
}

// add seg1 partials into C (all split tiles strictly sub-diagonal)
__global__ __launch_bounds__(256)
void combine_scratch(float* __restrict__ C)
{
    const int idx = blockIdx.x * 256 + threadIdx.x;   // < NSPLIT_T*2*8192
    const int sid = idx >> 13;
    const int loc = idx & 8191;
    const int t    = sid >> 1;
    const int half = sid & 1;
    int g = (int)((sqrtf(8.0f * (float)t + 1.0f) - 1.0f) * 0.5f);
    while ((g + 1) * (g + 2) / 2 <= t) ++g;
    while (g * (g + 1) / 2 > t) --g;
    const int bj = t - g * (g + 1) / 2;
    const int bi = bj + (NB - 1) - g;
    const int r = bi * 128 + (loc >> 6);
    const int c = bj * 128 + half * 64 + (loc & 63);
    C[(size_t)r * NDIM + c] += g_S[idx];
}

extern "C" void kernel_launch(void* const* d_in, const int* in_sizes, int n_in,
                              void* d_out, int out_size) {
    const float* A = (const float*)d_in[0];
    const float* B = (const float*)d_in[1];
    float* C = (float*)d_out;

    cudaFuncSetAttribute(trimm_f16, cudaFuncAttributeMaxDynamicSharedMemorySize,
                         SMEM_DYN);

    // zero output (kernel never writes the strict upper triangle)
    cudaMemsetAsync(C, 0, (size_t)NDIM * NDIM * sizeof(float), 0);

    const int nblocks = SPLIT_CTAS + (NB * (NB + 1) - 2 * NSPLIT_T);   // 1238
    trimm_f16<<<nblocks, THREADS, SMEM_DYN>>>(A, B, C);
    combine_scratch<<<NSPLIT_T * 2 * 8192 / 256, 256>>>(C);
}